// round 7
// baseline (speedup 1.0000x reference)
#include <cuda_runtime.h>
#include <math.h>

#define NN 4096
#define FH 256
#define CL 128
#define MAXDEG 128
#define MAXM 128
#define MAXC 64
#define MAXR (MAXDEG + MAXC)
#define CELLCAP 32
#define NEGINF (-1e9f)
#define KS 16

// ---------- scratch ----------
__device__ int   g_adj_idx[NN * MAXDEG];
__device__ int   g_adj_cnt[NN];
__device__ int   g_mf_idx[NN * MAXM];
__device__ float g_mf_val[NN * MAXM];
__device__ int   g_mf_cnt[NN];
__device__ float g_m_thr[NN];
__device__ int   g_m_idx[NN * MAXM];
__device__ float g_m_val[NN * MAXM];
__device__ int   g_m_cnt[NN];
__device__ float g_dinvM[NN];
__device__ float g_Wx[NN * FH];
__device__ float g_XWM[NN * FH];
__device__ float g_as[NN * 2];
__device__ float g_ad[NN * 2];
__device__ float g_h[NN * FH];
__device__ float g_pu[NN], g_pv[NN], g_ru[NN], g_rv[NN];
__device__ int   g_cell_cnt[4096];
__device__ int   g_cell_nodes[4096 * CELLCAP];
__device__ int   g_cand_idx[NN * MAXC];
__device__ float g_cand_z[NN * MAXC];
__device__ int   g_cand_cnt[NN];
__device__ float g_thr2[NN];
__device__ int   g_ref_idx[NN * MAXR];
__device__ float g_ref_w[NN * MAXR];
__device__ int   g_ref_cnt[NN];
__device__ float g_dinv_ref[NN];
__device__ float g_HW[NN * CL];
__device__ float g_S[NN * CL];
__device__ float g_T[NN * CL];
__device__ float g_Cpart[KS * 128 * 256];
__device__ float g_Cpart2[KS * 128 * 128];
__device__ float g_Ac[128 * 128];
__device__ float g_cthr[128];

// ---------- helpers ----------
__device__ __forceinline__ float hc_gate(float logit, float tau) {
    float t = fmaxf(tau, 0.1f);
    float s = 1.f / (1.f + expf(-logit / t));
    s = s * 1.2f - 0.1f;
    return fminf(fmaxf(s, 0.f), 1.f);
}
__device__ __forceinline__ float mhat_bs(int i, int j) {
    int c = g_m_cnt[i];
    const int* ip = &g_m_idx[i * MAXM];
    int lo = 0, hi = c;
    while (lo < hi) { int mid = (lo + hi) >> 1; if (ip[mid] < j) lo = mid + 1; else hi = mid; }
    return (lo < c && ip[lo] == j) ? g_m_val[i * MAXM + lo] : 0.f;
}

// ---------- device bodies (shared by fused kernels) ----------
__device__ void adj_row_body(const float* __restrict__ A, int gw, int lane) {
    const float4* row = (const float4*)(A + (size_t)gw * NN);
    unsigned below = (1u << lane) - 1;
    int c = 0;
    for (int b = 0; b < NN / 4; b += 32) {
        float4 v = row[b + lane];
        bool p0 = v.x > 0.f, p1 = v.y > 0.f, p2 = v.z > 0.f, p3 = v.w > 0.f;
        unsigned m0 = __ballot_sync(~0u, p0), m1 = __ballot_sync(~0u, p1);
        unsigned m2 = __ballot_sync(~0u, p2), m3 = __ballot_sync(~0u, p3);
        int base = c + __popc(m0 & below) + __popc(m1 & below) + __popc(m2 & below) + __popc(m3 & below);
        int col = (b + lane) * 4, o = 0;
        if (p0 && base + o < MAXDEG) g_adj_idx[gw * MAXDEG + base + o] = col;
        if (p0) o++;
        if (p1 && base + o < MAXDEG) g_adj_idx[gw * MAXDEG + base + o] = col + 1;
        if (p1) o++;
        if (p2 && base + o < MAXDEG) g_adj_idx[gw * MAXDEG + base + o] = col + 2;
        if (p2) o++;
        if (p3 && base + o < MAXDEG) g_adj_idx[gw * MAXDEG + base + o] = col + 3;
        c += __popc(m0) + __popc(m1) + __popc(m2) + __popc(m3);
    }
    if (lane == 0) g_adj_cnt[gw] = min(c, MAXDEG);
}

__device__ void motif_row_body(const float* __restrict__ A, int gw, int lane) {
    const float4* row = (const float4*)(A + (size_t)gw * NN);
    unsigned below = (1u << lane) - 1;
    int c = 0;
    for (int b = 0; b < NN / 4; b += 32) {
        float4 v = row[b + lane];
        bool p0 = v.x > 0.f, p1 = v.y > 0.f, p2 = v.z > 0.f, p3 = v.w > 0.f;
        unsigned m0 = __ballot_sync(~0u, p0), m1 = __ballot_sync(~0u, p1);
        unsigned m2 = __ballot_sync(~0u, p2), m3 = __ballot_sync(~0u, p3);
        int base = c + __popc(m0 & below) + __popc(m1 & below) + __popc(m2 & below) + __popc(m3 & below);
        int col = (b + lane) * 4, o = 0;
        if (p0 && base + o < MAXM) { g_mf_idx[gw * MAXM + base + o] = col;     g_mf_val[gw * MAXM + base + o] = v.x; }
        if (p0) o++;
        if (p1 && base + o < MAXM) { g_mf_idx[gw * MAXM + base + o] = col + 1; g_mf_val[gw * MAXM + base + o] = v.y; }
        if (p1) o++;
        if (p2 && base + o < MAXM) { g_mf_idx[gw * MAXM + base + o] = col + 2; g_mf_val[gw * MAXM + base + o] = v.z; }
        if (p2) o++;
        if (p3 && base + o < MAXM) { g_mf_idx[gw * MAXM + base + o] = col + 3; g_mf_val[gw * MAXM + base + o] = v.w; }
        c += __popc(m0) + __popc(m1) + __popc(m2) + __popc(m3);
    }
    c = min(c, MAXM);
    __syncwarp();
    float vv[4];
    #pragma unroll
    for (int s = 0; s < 4; s++) {
        int t = s * 32 + lane;
        vv[s] = (t < c) ? g_mf_val[gw * MAXM + t] : -2.f;
    }
    float thr = 0.f;
    if (c > 8) {
        for (int r = 0; r < 8; r++) {
            float lm = fmaxf(fmaxf(vv[0], vv[1]), fmaxf(vv[2], vv[3]));
            float wm = lm;
            for (int o = 16; o; o >>= 1) wm = fmaxf(wm, __shfl_xor_sync(~0u, wm, o));
            unsigned who = __ballot_sync(~0u, lm == wm);
            if (lane == (__ffs(who) - 1)) {
                #pragma unroll
                for (int s = 0; s < 4; s++) if (vv[s] == wm) { vv[s] = -2.f; break; }
            }
            thr = wm;
        }
    }
    if (lane == 0) { g_mf_cnt[gw] = c; g_m_thr[gw] = thr; }
}

// tiled SGEMM tile body: C[bm:bm+64, bn:bn+64] = A[M,K] @ B[K,Nc]
__device__ void gemm_body(const float* __restrict__ A, const float* __restrict__ B,
                          float* __restrict__ C, int M, int Nc, int K,
                          int bm, int bn, float (*As)[65], float (*Bs)[65]) {
    int tid = threadIdx.x, tr = tid >> 4, tc = tid & 15;
    float acc[4][4] = {};
    for (int k0 = 0; k0 < K; k0 += 16) {
        #pragma unroll
        for (int l = 0; l < 4; l++) {
            int e = tid + l * 256;
            int m = e >> 4, kk = e & 15;
            As[kk][m] = A[(size_t)(bm + m) * K + k0 + kk];
            int kk2 = e >> 6, n = e & 63;
            Bs[kk2][n] = B[(size_t)(k0 + kk2) * Nc + bn + n];
        }
        __syncthreads();
        #pragma unroll
        for (int kk = 0; kk < 16; kk++) {
            float a[4], b[4];
            #pragma unroll
            for (int r = 0; r < 4; r++) a[r] = As[kk][tr * 4 + r];
            #pragma unroll
            for (int c = 0; c < 4; c++) b[c] = Bs[kk][tc * 4 + c];
            #pragma unroll
            for (int r = 0; r < 4; r++)
                #pragma unroll
                for (int c = 0; c < 4; c++) acc[r][c] += a[r] * b[c];
        }
        __syncthreads();
    }
    #pragma unroll
    for (int r = 0; r < 4; r++)
        #pragma unroll
        for (int c = 0; c < 4; c++)
            C[(size_t)(bm + tr * 4 + r) * Nc + bn + tc * 4 + c] = acc[r][c];
}

// TN split-K tile body: Cpart[ks][bm.., bn..] = A[kslice,:]^T @ B[kslice,:]
__device__ void gemm_tn_body(const float* __restrict__ A, const float* __restrict__ B,
                             float* __restrict__ Cpart, int M, int Nc, int K,
                             int ks, int bm, int bn, float (*As)[65], float (*Bs)[65]) {
    int kbeg = ks * (K / KS), kend = kbeg + K / KS;
    int tid = threadIdx.x, tr = tid >> 4, tc = tid & 15;
    float acc[4][4] = {};
    for (int k0 = kbeg; k0 < kend; k0 += 16) {
        #pragma unroll
        for (int l = 0; l < 4; l++) {
            int e = tid + l * 256;
            int kk = e >> 6, n = e & 63;
            As[kk][n] = A[(size_t)(k0 + kk) * M + bm + n];
            Bs[kk][n] = B[(size_t)(k0 + kk) * Nc + bn + n];
        }
        __syncthreads();
        #pragma unroll
        for (int kk = 0; kk < 16; kk++) {
            float a[4], b[4];
            #pragma unroll
            for (int r = 0; r < 4; r++) a[r] = As[kk][tr * 4 + r];
            #pragma unroll
            for (int c = 0; c < 4; c++) b[c] = Bs[kk][tc * 4 + c];
            #pragma unroll
            for (int r = 0; r < 4; r++)
                #pragma unroll
                for (int c = 0; c < 4; c++) acc[r][c] += a[r] * b[c];
        }
        __syncthreads();
    }
    float* Cp = Cpart + (size_t)ks * M * Nc;
    #pragma unroll
    for (int r = 0; r < 4; r++)
        #pragma unroll
        for (int c = 0; c < 4; c++)
            Cp[(size_t)(bm + tr * 4 + r) * Nc + bn + tc * 4 + c] = acc[r][c];
}

// ---------- L1: scans + zero cells ----------
__global__ void k_scan(const float* __restrict__ A_in, const float* __restrict__ A_motif) {
    int b = blockIdx.x, lane = threadIdx.x & 31, wid = threadIdx.x >> 5;
    if (b < 16) {
        int t = b * 256 + threadIdx.x;
        g_cell_cnt[t] = 0;
    }
    if (b < 512) {
        adj_row_body(A_in, b * 8 + wid, lane);
    } else {
        motif_row_body(A_motif, (b - 512) * 8 + wid, lane);
    }
}

// ---------- L2: mfilter + cells insert ----------
__global__ void k_mfilter_cells(const float* __restrict__ coords) {
    int b = blockIdx.x;
    if (b >= 512) {  // cells insert, 16 blocks
        int i = (b - 512) * 256 + threadIdx.x;
        int cx = (int)coords[2 * i], cy = (int)coords[2 * i + 1];
        int p = atomicAdd(&g_cell_cnt[cx * 64 + cy], 1);
        if (p < CELLCAP) g_cell_nodes[(cx * 64 + cy) * CELLCAP + p] = i;
        return;
    }
    int gw = b * 8 + (threadIdx.x >> 5), lane = threadIdx.x & 31;
    int i = gw, cnt = g_mf_cnt[i], out = 0;
    float thrI = g_m_thr[i], wsum = 0.f;
    for (int base = 0; base < cnt; base += 32) {
        int t = base + lane; bool ok = t < cnt; int j = 0; float v = 0.f;
        if (ok) {
            j = g_mf_idx[i * MAXM + t]; v = g_mf_val[i * MAXM + t];
            ok = (v >= thrI) || (v >= g_m_thr[j]);
        }
        unsigned m = __ballot_sync(0xffffffffu, ok);
        int pos = out + __popc(m & ((1u << lane) - 1));
        if (ok) { g_m_idx[i * MAXM + pos] = j; g_m_val[i * MAXM + pos] = v; wsum += v; }
        out += __popc(m);
    }
    for (int o = 16; o; o >>= 1) wsum += __shfl_down_sync(0xffffffffu, wsum, o);
    if (lane == 0) { g_m_cnt[i] = out; g_dinvM[i] = (wsum > 0.f) ? rsqrtf(wsum) : 0.f; }
}

// ---------- L3: two feature GEMMs in one launch ----------
__global__ void k_gemm2(const float* __restrict__ x, const float* __restrict__ gat_w,
                        const float* __restrict__ gcnMw, float* __restrict__ Wx,
                        float* __restrict__ XWM) {
    __shared__ float As[16][65], Bs[16][65];
    int bm = blockIdx.y * 64, bn = blockIdx.x * 64;
    if (blockIdx.z == 0) gemm_body(x, gat_w, Wx, NN, FH, 128, bm, bn, As, Bs);
    else                 gemm_body(x, gcnMw, XWM, NN, FH, 128, bm, bn, As, Bs);
}

// ---------- L4: attn coefficients + cell sort ----------
__global__ void k_attn_sort(const float* __restrict__ asw, const float* __restrict__ adw) {
    int b = blockIdx.x;
    if (b >= 1024) {  // cells_sort, 16 blocks
        int c = (b - 1024) * 256 + threadIdx.x;
        int n = min(g_cell_cnt[c], CELLCAP);
        int* a = &g_cell_nodes[c * CELLCAP];
        for (int x = 1; x < n; x++) {
            int v = a[x], y = x - 1;
            while (y >= 0 && a[y] > v) { a[y + 1] = a[y]; y--; }
            a[y + 1] = v;
        }
        return;
    }
    int gw = b * 8 + (threadIdx.x >> 5), lane = threadIdx.x & 31;
    int node = gw >> 1, hh = gw & 1;
    const float* row = g_Wx + (size_t)node * FH + hh * 128;
    float s = 0.f, d = 0.f;
    for (int k = lane; k < 128; k += 32) {
        float w = row[k];
        s += w * asw[hh * 128 + k];
        d += w * adw[hh * 128 + k];
    }
    for (int o = 16; o; o >>= 1) {
        s += __shfl_down_sync(0xffffffffu, s, o);
        d += __shfl_down_sync(0xffffffffu, d, o);
    }
    if (lane == 0) { g_as[node * 2 + hh] = s; g_ad[node * 2 + hh] = d; }
}

// ---------- L5: aggregate (paired reductions; same fp tree order) ----------
__global__ void k_aggregate(
    const float* __restrict__ gat_b,
    const float* __restrict__ bnAg, const float* __restrict__ bnAb,
    const float* __restrict__ bnAm, const float* __restrict__ bnAv,
    const float* __restrict__ gcnMb,
    const float* __restrict__ bnMg, const float* __restrict__ bnMb,
    const float* __restrict__ bnMm, const float* __restrict__ bnMv,
    const float* __restrict__ mu_, const float* __restrict__ prune_w,
    const float* __restrict__ rewire_w)
{
    __shared__ int sj[MAXDEG + 1];
    __shared__ float se0[MAXDEG + 1], se1[MAXDEG + 1];
    __shared__ int smj[MAXM];
    __shared__ float smc[MAXM];
    __shared__ float rA[256], rB[256];
    int i = blockIdx.x, tid = threadIdx.x;
    int deg = g_adj_cnt[i], tot = deg + 1;
    float ad0 = g_ad[2 * i], ad1 = g_ad[2 * i + 1];
    for (int t = tid; t < tot; t += 256) {
        int j = (t < deg) ? g_adj_idx[i * MAXDEG + t] : i;
        sj[t] = j;
        float e0 = ad0 + g_as[2 * j], e1 = ad1 + g_as[2 * j + 1];
        se0[t] = (e0 > 0.f) ? e0 : 0.2f * e0;
        se1[t] = (e1 > 0.f) ? e1 : 0.2f * e1;
    }
    int mc = g_m_cnt[i];
    for (int t = tid; t < mc; t += 256) {
        int j = g_m_idx[i * MAXM + t];
        smj[t] = j;
        smc[t] = g_m_val[i * MAXM + t] * g_dinvM[j];
    }
    __syncthreads();
    float lm0 = -3.4e38f, lm1 = -3.4e38f;
    for (int t = tid; t < tot; t += 256) { lm0 = fmaxf(lm0, se0[t]); lm1 = fmaxf(lm1, se1[t]); }
    rA[tid] = lm0; rB[tid] = lm1; __syncthreads();
    for (int s = 128; s > 0; s >>= 1) {
        if (tid < s) { rA[tid] = fmaxf(rA[tid], rA[tid + s]); rB[tid] = fmaxf(rB[tid], rB[tid + s]); }
        __syncthreads();
    }
    float M0 = rA[0], M1 = rB[0]; __syncthreads();
    float ls0 = 0.f, ls1 = 0.f;
    for (int t = tid; t < tot; t += 256) {
        float e0 = expf(se0[t] - M0); se0[t] = e0; ls0 += e0;
        float e1 = expf(se1[t] - M1); se1[t] = e1; ls1 += e1;
    }
    rA[tid] = ls0; rB[tid] = ls1; __syncthreads();
    for (int s = 128; s > 0; s >>= 1) {
        if (tid < s) { rA[tid] += rA[tid + s]; rB[tid] += rB[tid + s]; }
        __syncthreads();
    }
    float D0 = rA[0], D1 = rB[0]; __syncthreads();

    int d = tid, head = d >> 7;
    float Dh = head ? D1 : D0;
    const float* se = head ? se1 : se0;
    float accA = 0.f;
    #pragma unroll 4
    for (int k = 0; k < tot; k++) accA += se[k] * g_Wx[(size_t)sj[k] * FH + d];
    float hA = accA / Dh + gat_b[d];
    hA = (hA - bnAm[d]) * bnAg[d] * rsqrtf(bnAv[d] + 1e-5f) + bnAb[d];
    hA = (hA > 0.f) ? hA : expm1f(hA);

    float accM = 0.f;
    #pragma unroll 4
    for (int k = 0; k < mc; k++) accM += smc[k] * g_XWM[(size_t)smj[k] * FH + d];
    float hM = g_dinvM[i] * accM + gcnMb[d];
    hM = (hM - bnMm[d]) * bnMg[d] * rsqrtf(bnMv[d] + 1e-5f) + bnMb[d];
    hM = (hM > 0.f) ? hM : expm1f(hM);

    float mu = mu_[0];
    float sp = (mu > 20.f) ? mu : log1pf(expf(mu));
    float hv = hA + sp * hM;
    g_h[(size_t)i * FH + d] = hv;

    // pu & pv (paired tree, same order as before)
    rA[tid] = hv * prune_w[d]; rB[tid] = hv * prune_w[256 + d]; __syncthreads();
    for (int s = 128; s > 0; s >>= 1) {
        if (tid < s) { rA[tid] += rA[tid + s]; rB[tid] += rB[tid + s]; }
        __syncthreads();
    }
    float r0 = rA[0], r1 = rB[0]; __syncthreads();
    rA[tid] = hv * rewire_w[d]; rB[tid] = hv * rewire_w[256 + d]; __syncthreads();
    for (int s = 128; s > 0; s >>= 1) {
        if (tid < s) { rA[tid] += rA[tid + s]; rB[tid] += rB[tid + s]; }
        __syncthreads();
    }
    if (tid == 0) { g_pu[i] = r0; g_pv[i] = r1; g_ru[i] = rA[0]; g_rv[i] = rB[0]; }
}

// ---------- L6: candidates (warp/node) + HW GEMM ----------
__global__ void k_cand_hw(const float* __restrict__ coords, const float* __restrict__ A_in,
                          const float* __restrict__ rw, const float* __restrict__ rb_,
                          const float* __restrict__ tau_, const float* __restrict__ pool_w) {
    __shared__ float As[16][65], Bs[16][65];
    int b = blockIdx.x;
    if (b >= 512) {  // HW = h @ pool_w : grid 2 x 64 -> 128 blocks
        int bidx = b - 512;
        int bn = (bidx & 1) * 64, bm = (bidx >> 1) * 64;
        gemm_body(g_h, pool_w, g_HW, NN, CL, FH, bm, bn, As, Bs);
        return;
    }
    int gw = b * 8 + (threadIdx.x >> 5), lane = threadIdx.x & 31;
    int i = gw;
    float tau = tau_[0], rw2 = rw[512], rb = rb_[0];
    int cx = (int)coords[2 * i], cy = (int)coords[2 * i + 1];
    const int ox[12] = {-2,-1,-1,-1, 0, 0, 0, 0, 1, 1, 1, 2};
    const int oy[12] = { 0,-1, 0, 1,-2,-1, 1, 2,-1, 0, 1, 0};
    float rui = g_ru[i], rvi = g_rv[i];
    int cnt = 0;
    float m1 = NEGINF, m2 = NEGINF;
    for (int o = 0; o < 12; o++) {
        int nx = cx + ox[o], ny = cy + oy[o];
        if (nx < 0 || nx >= 64 || ny < 0 || ny >= 64) continue;
        int cell = nx * 64 + ny;
        int cc = min(g_cell_cnt[cell], CELLCAP);
        for (int base = 0; base < cc; base += 32) {
            int t = base + lane;
            bool ok = t < cc;
            int j = 0; float z = 0.f;
            if (ok) {
                j = g_cell_nodes[cell * CELLCAP + t];
                ok = A_in[(size_t)i * NN + j] < 1e-6f;
            }
            if (ok) {
                float ruv = (i < j) ? (rui + g_rv[j]) : (g_ru[j] + rvi);
                z = hc_gate(ruv + rw2 * mhat_bs(i, j) + rb, tau);
                if (z > m1) { m2 = m1; m1 = z; } else if (z > m2) { m2 = z; }
            }
            unsigned m = __ballot_sync(~0u, ok);
            int pos = cnt + __popc(m & ((1u << lane) - 1));
            if (ok && pos < MAXC) { g_cand_idx[i * MAXC + pos] = j; g_cand_z[i * MAXC + pos] = z; }
            cnt += __popc(m);
        }
    }
    for (int o = 16; o; o >>= 1) {
        float om1 = __shfl_xor_sync(~0u, m1, o);
        float om2 = __shfl_xor_sync(~0u, m2, o);
        float hi = fmaxf(m1, om1), lo = fminf(m1, om1);
        m2 = fmaxf(lo, fmaxf(m2, om2));
        m1 = hi;
    }
    if (lane == 0) { g_cand_cnt[i] = min(cnt, MAXC); g_thr2[i] = m2; }
}

// ---------- L7: refined adjacency ----------
__global__ void k_refined(const float* __restrict__ prune_w, const float* __restrict__ prune_b,
                          const float* __restrict__ tau_) {
    int gw = blockIdx.x * 8 + (threadIdx.x >> 5), lane = threadIdx.x & 31;
    int i = gw;
    float tau = tau_[0], pw2 = prune_w[512], pb = prune_b[0];
    int deg = g_adj_cnt[i];
    float wsum = 0.f;
    for (int t = lane; t < deg; t += 32) {
        int j = g_adj_idx[i * MAXDEG + t];
        float puv = (i < j) ? (g_pu[i] + g_pv[j]) : (g_pu[j] + g_pv[i]);
        float z = hc_gate(puv + pw2 * mhat_bs(i, j) + pb, tau);
        g_ref_idx[i * MAXR + t] = j;
        g_ref_w[i * MAXR + t] = z;
        wsum += z;
    }
    int cnt = deg;
    float thrI = g_thr2[i];
    int cc = g_cand_cnt[i];
    for (int base = 0; base < cc; base += 32) {
        int t = base + lane; bool ok = false; int j = 0; float z = 0.f;
        if (t < cc) {
            j = g_cand_idx[i * MAXC + t]; z = g_cand_z[i * MAXC + t];
            ok = (z >= thrI) || (z >= g_thr2[j]);
        }
        unsigned m = __ballot_sync(0xffffffffu, ok);
        int pos = cnt + __popc(m & ((1u << lane) - 1));
        if (ok) { g_ref_idx[i * MAXR + pos] = j; g_ref_w[i * MAXR + pos] = 0.5f * z; wsum += 0.5f * z; }
        cnt += __popc(m);
    }
    for (int o = 16; o; o >>= 1) wsum += __shfl_down_sync(0xffffffffu, wsum, o);
    if (lane == 0) { g_ref_cnt[i] = cnt; g_dinv_ref[i] = rsqrtf(wsum + 1.f); }
}

// ---------- L8: pooling softmax ----------
__global__ void k_pool(const float* __restrict__ pool_b) {
    __shared__ float red[128];
    int i = blockIdx.x, c = threadIdx.x;
    float di = g_dinv_ref[i];
    int cnt = g_ref_cnt[i];
    float acc = di * g_HW[(size_t)i * CL + c];
    #pragma unroll 4
    for (int t = 0; t < cnt; t++) {
        int j = g_ref_idx[i * MAXR + t];
        acc += g_ref_w[i * MAXR + t] * g_dinv_ref[j] * g_HW[(size_t)j * CL + c];
    }
    float pre = di * acc + pool_b[c];
    red[c] = pre; __syncthreads();
    for (int s = 64; s > 0; s >>= 1) { if (c < s) red[c] = fmaxf(red[c], red[c + s]); __syncthreads(); }
    float mx = red[0]; __syncthreads();
    float e = expf(pre - mx);
    red[c] = e; __syncthreads();
    for (int s = 64; s > 0; s >>= 1) { if (c < s) red[c] += red[c + s]; __syncthreads(); }
    g_S[(size_t)i * CL + c] = e / red[0];
}

// ---------- L9: T = A_ref @ S  (2 rows/block)  +  gemm_tn(S, h) ----------
__global__ void k_spmm_tn() {
    __shared__ float As[16][65], Bs[16][65];
    int b = blockIdx.x;
    if (b >= 2048) {  // gemm_tn (S, h): grid 4 x 2 x 16 -> 128 blocks
        int bidx = b - 2048;
        int ks = bidx >> 3;
        int bn = (bidx & 3) * 64, bm = ((bidx >> 2) & 1) * 64;
        gemm_tn_body(g_S, g_h, g_Cpart, 128, FH, NN, ks, bm, bn, As, Bs);
        return;
    }
    int i = b * 2 + (threadIdx.x >> 7);
    int c = threadIdx.x & 127;
    int cnt = g_ref_cnt[i];
    float acc = 0.f;
    #pragma unroll 4
    for (int t = 0; t < cnt; t++)
        acc += g_ref_w[i * MAXR + t] * g_S[(size_t)g_ref_idx[i * MAXR + t] * CL + c];
    g_T[(size_t)i * CL + c] = acc;
}

// ---------- L10: reduce X_coarse to out  +  gemm_tn(S, T) ----------
__global__ void k_red_tn(float* __restrict__ out) {
    __shared__ float As[16][65], Bs[16][65];
    int b = blockIdx.x;
    if (b >= 128) {  // gemm_tn (S, T): grid 2 x 2 x 16 -> 64 blocks
        int bidx = b - 128;
        int ks = bidx >> 2;
        int bn = (bidx & 1) * 64, bm = ((bidx >> 1) & 1) * 64;
        gemm_tn_body(g_S, g_T, g_Cpart2, 128, CL, NN, ks, bm, bn, As, Bs);
        return;
    }
    int t = b * 256 + threadIdx.x;   // 128*256 = 32768 = 128*FH
    float s = 0.f;
    #pragma unroll
    for (int z = 0; z < KS; z++) s += g_Cpart[(size_t)z * 128 * FH + t];
    out[t] = s;
}

// ---------- L11: reduce Ac + per-row top-8 threshold ----------
__global__ void k_reduce_ac() {
    __shared__ float sv[128];
    __shared__ float smax;
    __shared__ int sidx;
    int i = blockIdx.x, j = threadIdx.x;   // 128 blocks x 128 threads
    float s = 0.f;
    #pragma unroll
    for (int z = 0; z < KS; z++) s += g_Cpart2[(size_t)z * 128 * 128 + i * 128 + j];
    g_Ac[i * 128 + j] = s;
    sv[j] = (j == i) ? 0.f : s;
    __syncthreads();
    float thr = 0.f;
    for (int r = 0; r < 8; r++) {
        // block max
        if (j == 0) { smax = -1e30f; sidx = 1 << 30; }
        __syncthreads();
        // two-phase: warp maxes then atomic-free merge via shared scan
        float v = sv[j];
        for (int o = 16; o; o >>= 1) v = fmaxf(v, __shfl_xor_sync(~0u, v, o));
        if ((j & 31) == 0) atomicMaxFloatDummy: ;
        // simple: use shared reduction array reuse sv? need sv intact. Use warp results:
        __shared__ float wmax[4];
        if ((j & 31) == 0) wmax[j >> 5] = v;
        __syncthreads();
        float bm = fmaxf(fmaxf(wmax[0], wmax[1]), fmaxf(wmax[2], wmax[3]));
        // lowest index holding bm removes itself
        if (sv[j] == bm) atomicMin(&sidx, j);
        __syncthreads();
        if (j == sidx) sv[j] = -1e30f;
        thr = bm;
        __syncthreads();
        if (j == 0) sidx = 1 << 30;
        __syncthreads();
    }
    if (j == 0) g_cthr[i] = thr;
}

// ---------- L12: final coarse write ----------
__global__ void k_coarse_write(float* __restrict__ out) {
    int t = blockIdx.x * blockDim.x + threadIdx.x;
    if (t >= 128 * 128) return;
    int i = t >> 7, j = t & 127;
    if (i == j) { out[t] = 0.f; return; }
    float vij = g_Ac[i * 128 + j];
    float vji = g_Ac[j * 128 + i];
    float a = (vij >= g_cthr[i]) ? vij : 0.f;
    float b = (vji >= g_cthr[j]) ? vji : 0.f;
    out[t] = fmaxf(a, b);
}

// ---------- host ----------
extern "C" void kernel_launch(void* const* d_in, const int* in_sizes, int n_in,
                              void* d_out, int out_size) {
    const float* x       = (const float*)d_in[0];
    const float* A_in    = (const float*)d_in[1];
    const float* A_motif = (const float*)d_in[2];
    const float* coords  = (const float*)d_in[3];
    const float* gat_w   = (const float*)d_in[4];
    const float* gat_as  = (const float*)d_in[5];
    const float* gat_ad  = (const float*)d_in[6];
    const float* gat_b   = (const float*)d_in[7];
    const float* bnAg = (const float*)d_in[8],  *bnAb = (const float*)d_in[9];
    const float* bnAm = (const float*)d_in[10], *bnAv = (const float*)d_in[11];
    const float* gcnMw = (const float*)d_in[12], *gcnMb = (const float*)d_in[13];
    const float* bnMg = (const float*)d_in[14], *bnMb = (const float*)d_in[15];
    const float* bnMm = (const float*)d_in[16], *bnMv = (const float*)d_in[17];
    const float* mu   = (const float*)d_in[18], *tau  = (const float*)d_in[19];
    const float* prune_w = (const float*)d_in[20], *prune_b = (const float*)d_in[21];
    const float* rewire_w = (const float*)d_in[22], *rewire_b = (const float*)d_in[23];
    const float* pool_w = (const float*)d_in[24], *pool_b = (const float*)d_in[25];
    float* out = (float*)d_out;

    float *Wx, *XWM;
    cudaGetSymbolAddress((void**)&Wx, g_Wx);
    cudaGetSymbolAddress((void**)&XWM, g_XWM);

    k_scan<<<1024, 256>>>(A_in, A_motif);                      // L1
    k_mfilter_cells<<<528, 256>>>(coords);                     // L2
    k_gemm2<<<dim3(4, 64, 2), 256>>>(x, gat_w, gcnMw, Wx, XWM);// L3
    k_attn_sort<<<1040, 256>>>(gat_as, gat_ad);                // L4
    k_aggregate<<<NN, 256>>>(gat_b, bnAg, bnAb, bnAm, bnAv, gcnMb,
                             bnMg, bnMb, bnMm, bnMv, mu, prune_w, rewire_w); // L5
    k_cand_hw<<<640, 256>>>(coords, A_in, rewire_w, rewire_b, tau, pool_w);  // L6
    k_refined<<<512, 256>>>(prune_w, prune_b, tau);            // L7
    k_pool<<<NN, 128>>>(pool_b);                               // L8
    k_spmm_tn<<<2176, 256>>>();                                // L9
    k_red_tn<<<192, 256>>>(out);                               // L10
    k_reduce_ac<<<128, 128>>>();                               // L11
    k_coarse_write<<<64, 256>>>(out + 128 * FH);               // L12
}

// round 8
// speedup vs baseline: 1.0480x; 1.0480x over previous
#include <cuda_runtime.h>
#include <math.h>

#define NN 4096
#define FH 256
#define CL 128
#define MAXDEG 128
#define MAXM 128
#define MAXC 64
#define MAXR (MAXDEG + MAXC)
#define CELLCAP 32
#define NEGINF (-1e9f)
#define KS 16

// ---------- scratch ----------
__device__ int   g_adj_idx[NN * MAXDEG];
__device__ int   g_adj_cnt[NN];
__device__ int   g_mf_idx[NN * MAXM];
__device__ float g_mf_val[NN * MAXM];
__device__ int   g_mf_cnt[NN];
__device__ float g_m_thr[NN];
__device__ int   g_m_idx[NN * MAXM];
__device__ float g_m_val[NN * MAXM];
__device__ int   g_m_cnt[NN];
__device__ float g_dinvM[NN];
__device__ float g_Wx[NN * FH];
__device__ float g_XWM[NN * FH];
__device__ float g_as[NN * 2];
__device__ float g_ad[NN * 2];
__device__ float g_h[NN * FH];
__device__ float g_pu[NN], g_pv[NN], g_ru[NN], g_rv[NN];
__device__ int   g_cell_cnt[4096];
__device__ int   g_cell_nodes[4096 * CELLCAP];
__device__ int   g_cand_idx[NN * MAXC];
__device__ float g_cand_z[NN * MAXC];
__device__ int   g_cand_cnt[NN];
__device__ float g_thr2[NN];
__device__ int   g_ref_idx[NN * MAXR];
__device__ float g_ref_w[NN * MAXR];
__device__ int   g_ref_cnt[NN];
__device__ float g_dinv_ref[NN];
__device__ float g_HW[NN * CL];
__device__ float g_S[NN * CL];
__device__ float g_T[NN * CL];
__device__ float g_Cpart[KS * 128 * 256];
__device__ float g_Ac[128 * 128];
__device__ float g_cthr[128];

// ---------- helpers ----------
__device__ __forceinline__ float hc_gate(float logit, float tau) {
    float t = fmaxf(tau, 0.1f);
    float s = 1.f / (1.f + expf(-logit / t));
    s = s * 1.2f - 0.1f;
    return fminf(fmaxf(s, 0.f), 1.f);
}
__device__ __forceinline__ float mhat_bs(int i, int j) {
    int c = g_m_cnt[i];
    const int* ip = &g_m_idx[i * MAXM];
    int lo = 0, hi = c;
    while (lo < hi) { int mid = (lo + hi) >> 1; if (ip[mid] < j) lo = mid + 1; else hi = mid; }
    return (lo < c && ip[lo] == j) ? g_m_val[i * MAXM + lo] : 0.f;
}

// ---------- kernels ----------
// warp per row; blocks 0-15 also zero g_cell_cnt (saves a launch)
__global__ void k_build_adj(const float* __restrict__ A) {
    if (blockIdx.x < 16) g_cell_cnt[blockIdx.x * 256 + threadIdx.x] = 0;
    int gw = (blockIdx.x * blockDim.x + threadIdx.x) >> 5;
    int lane = threadIdx.x & 31;
    if (gw >= NN) return;
    const float4* row = (const float4*)(A + (size_t)gw * NN);
    unsigned below = (1u << lane) - 1;
    int c = 0;
    #pragma unroll 4
    for (int b = 0; b < NN / 4; b += 32) {
        float4 v = row[b + lane];
        bool p0 = v.x > 0.f, p1 = v.y > 0.f, p2 = v.z > 0.f, p3 = v.w > 0.f;
        unsigned m0 = __ballot_sync(~0u, p0), m1 = __ballot_sync(~0u, p1);
        unsigned m2 = __ballot_sync(~0u, p2), m3 = __ballot_sync(~0u, p3);
        int base = c + __popc(m0 & below) + __popc(m1 & below) + __popc(m2 & below) + __popc(m3 & below);
        int col = (b + lane) * 4, o = 0;
        if (p0 && base + o < MAXDEG) g_adj_idx[gw * MAXDEG + base + o] = col;
        if (p0) o++;
        if (p1 && base + o < MAXDEG) g_adj_idx[gw * MAXDEG + base + o] = col + 1;
        if (p1) o++;
        if (p2 && base + o < MAXDEG) g_adj_idx[gw * MAXDEG + base + o] = col + 2;
        if (p2) o++;
        if (p3 && base + o < MAXDEG) g_adj_idx[gw * MAXDEG + base + o] = col + 3;
        c += __popc(m0) + __popc(m1) + __popc(m2) + __popc(m3);
    }
    if (lane == 0) g_adj_cnt[gw] = min(c, MAXDEG);
}

__global__ void k_build_motif(const float* __restrict__ A) {
    int gw = (blockIdx.x * blockDim.x + threadIdx.x) >> 5;
    int lane = threadIdx.x & 31;
    if (gw >= NN) return;
    const float4* row = (const float4*)(A + (size_t)gw * NN);
    unsigned below = (1u << lane) - 1;
    int c = 0;
    #pragma unroll 4
    for (int b = 0; b < NN / 4; b += 32) {
        float4 v = row[b + lane];
        bool p0 = v.x > 0.f, p1 = v.y > 0.f, p2 = v.z > 0.f, p3 = v.w > 0.f;
        unsigned m0 = __ballot_sync(~0u, p0), m1 = __ballot_sync(~0u, p1);
        unsigned m2 = __ballot_sync(~0u, p2), m3 = __ballot_sync(~0u, p3);
        int base = c + __popc(m0 & below) + __popc(m1 & below) + __popc(m2 & below) + __popc(m3 & below);
        int col = (b + lane) * 4, o = 0;
        if (p0 && base + o < MAXM) { g_mf_idx[gw * MAXM + base + o] = col;     g_mf_val[gw * MAXM + base + o] = v.x; }
        if (p0) o++;
        if (p1 && base + o < MAXM) { g_mf_idx[gw * MAXM + base + o] = col + 1; g_mf_val[gw * MAXM + base + o] = v.y; }
        if (p1) o++;
        if (p2 && base + o < MAXM) { g_mf_idx[gw * MAXM + base + o] = col + 2; g_mf_val[gw * MAXM + base + o] = v.z; }
        if (p2) o++;
        if (p3 && base + o < MAXM) { g_mf_idx[gw * MAXM + base + o] = col + 3; g_mf_val[gw * MAXM + base + o] = v.w; }
        c += __popc(m0) + __popc(m1) + __popc(m2) + __popc(m3);
    }
    c = min(c, MAXM);
    __syncwarp();
    float vv[4];
    #pragma unroll
    for (int s = 0; s < 4; s++) {
        int t = s * 32 + lane;
        vv[s] = (t < c) ? g_mf_val[gw * MAXM + t] : -2.f;
    }
    float thr = 0.f;
    if (c > 8) {
        for (int r = 0; r < 8; r++) {
            float lm = fmaxf(fmaxf(vv[0], vv[1]), fmaxf(vv[2], vv[3]));
            float wm = lm;
            for (int o = 16; o; o >>= 1) wm = fmaxf(wm, __shfl_xor_sync(~0u, wm, o));
            unsigned who = __ballot_sync(~0u, lm == wm);
            if (lane == (__ffs(who) - 1)) {
                #pragma unroll
                for (int s = 0; s < 4; s++) if (vv[s] == wm) { vv[s] = -2.f; break; }
            }
            thr = wm;
        }
    }
    if (lane == 0) { g_mf_cnt[gw] = c; g_m_thr[gw] = thr; }
}

__global__ void k_mfilter() {
    int gw = (blockIdx.x * blockDim.x + threadIdx.x) >> 5;
    int lane = threadIdx.x & 31;
    if (gw >= NN) return;
    int i = gw, cnt = g_mf_cnt[i], out = 0;
    float thrI = g_m_thr[i], wsum = 0.f;
    for (int base = 0; base < cnt; base += 32) {
        int t = base + lane; bool ok = t < cnt; int j = 0; float v = 0.f;
        if (ok) {
            j = g_mf_idx[i * MAXM + t]; v = g_mf_val[i * MAXM + t];
            ok = (v >= thrI) || (v >= g_m_thr[j]);
        }
        unsigned m = __ballot_sync(0xffffffffu, ok);
        int pos = out + __popc(m & ((1u << lane) - 1));
        if (ok) { g_m_idx[i * MAXM + pos] = j; g_m_val[i * MAXM + pos] = v; wsum += v; }
        out += __popc(m);
    }
    for (int o = 16; o; o >>= 1) wsum += __shfl_down_sync(0xffffffffu, wsum, o);
    if (lane == 0) { g_m_cnt[i] = out; g_dinvM[i] = (wsum > 0.f) ? rsqrtf(wsum) : 0.f; }
}

// C[M,Nc] = A[M,K] @ B[K,Nc]; 128x64 block tile, 8x4 micro; M mult 128,
// Nc mult 64, K mult 16. K-order identical to old kernel -> bit-identical.
__global__ void k_gemm(const float* __restrict__ A, const float* __restrict__ B,
                       float* __restrict__ C, int M, int Nc, int K) {
    __shared__ float As[16][132];
    __shared__ float Bs[16][68];
    int bm = blockIdx.y * 128, bn = blockIdx.x * 64;
    int tid = threadIdx.x, tr = tid >> 4, tc = tid & 15;
    float acc[8][4] = {};
    for (int k0 = 0; k0 < K; k0 += 16) {
        #pragma unroll
        for (int l = 0; l < 8; l++) {
            int e = tid + l * 256;
            int m = e >> 4, kk = e & 15;
            As[kk][m] = A[(size_t)(bm + m) * K + k0 + kk];
        }
        #pragma unroll
        for (int l = 0; l < 4; l++) {
            int e = tid + l * 256;
            int kk = e >> 6, n = e & 63;
            Bs[kk][n] = B[(size_t)(k0 + kk) * Nc + bn + n];
        }
        __syncthreads();
        #pragma unroll
        for (int kk = 0; kk < 16; kk++) {
            float a[8], b[4];
            #pragma unroll
            for (int r = 0; r < 8; r++) a[r] = As[kk][tr * 8 + r];
            #pragma unroll
            for (int c = 0; c < 4; c++) b[c] = Bs[kk][tc * 4 + c];
            #pragma unroll
            for (int r = 0; r < 8; r++)
                #pragma unroll
                for (int c = 0; c < 4; c++) acc[r][c] += a[r] * b[c];
        }
        __syncthreads();
    }
    #pragma unroll
    for (int r = 0; r < 8; r++)
        #pragma unroll
        for (int c = 0; c < 4; c++)
            C[(size_t)(bm + tr * 8 + r) * Nc + bn + tc * 4 + c] = acc[r][c];
}

// Cpart[ks][M,Nc] = A[kslice,M]^T @ B[kslice,Nc]
__global__ void k_gemm_tn(const float* __restrict__ A, const float* __restrict__ B,
                          float* __restrict__ Cpart, int M, int Nc, int K) {
    __shared__ float As[16][65], Bs[16][65];
    int ks = blockIdx.z, kbeg = ks * (K / KS), kend = kbeg + K / KS;
    int bm = blockIdx.y * 64, bn = blockIdx.x * 64;
    int tid = threadIdx.x, tr = tid >> 4, tc = tid & 15;
    float acc[4][4] = {};
    for (int k0 = kbeg; k0 < kend; k0 += 16) {
        #pragma unroll
        for (int l = 0; l < 4; l++) {
            int e = tid + l * 256;
            int kk = e >> 6, n = e & 63;
            As[kk][n] = A[(size_t)(k0 + kk) * M + bm + n];
            Bs[kk][n] = B[(size_t)(k0 + kk) * Nc + bn + n];
        }
        __syncthreads();
        #pragma unroll
        for (int kk = 0; kk < 16; kk++) {
            float a[4], b[4];
            #pragma unroll
            for (int r = 0; r < 4; r++) a[r] = As[kk][tr * 4 + r];
            #pragma unroll
            for (int c = 0; c < 4; c++) b[c] = Bs[kk][tc * 4 + c];
            #pragma unroll
            for (int r = 0; r < 4; r++)
                #pragma unroll
                for (int c = 0; c < 4; c++) acc[r][c] += a[r] * b[c];
        }
        __syncthreads();
    }
    float* Cp = Cpart + (size_t)ks * M * Nc;
    #pragma unroll
    for (int r = 0; r < 4; r++)
        #pragma unroll
        for (int c = 0; c < 4; c++)
            Cp[(size_t)(bm + tr * 4 + r) * Nc + bn + tc * 4 + c] = acc[r][c];
}

__global__ void k_reduce_part(float* __restrict__ dst, int MN) {
    int t = blockIdx.x * blockDim.x + threadIdx.x;
    if (t >= MN) return;
    float s = 0.f;
    for (int z = 0; z < KS; z++) s += g_Cpart[(size_t)z * MN + t];
    dst[t] = s;
}

__global__ void k_attn_coef(const float* __restrict__ asw, const float* __restrict__ adw) {
    int gw = (blockIdx.x * blockDim.x + threadIdx.x) >> 5;
    int lane = threadIdx.x & 31;
    if (gw >= NN * 2) return;
    int node = gw >> 1, hh = gw & 1;
    const float* row = g_Wx + (size_t)node * FH + hh * 128;
    float s = 0.f, d = 0.f;
    for (int k = lane; k < 128; k += 32) {
        float w = row[k];
        s += w * asw[hh * 128 + k];
        d += w * adw[hh * 128 + k];
    }
    for (int o = 16; o; o >>= 1) {
        s += __shfl_down_sync(0xffffffffu, s, o);
        d += __shfl_down_sync(0xffffffffu, d, o);
    }
    if (lane == 0) { g_as[node * 2 + hh] = s; g_ad[node * 2 + hh] = d; }
}

__global__ void k_aggregate(
    const float* __restrict__ gat_b,
    const float* __restrict__ bnAg, const float* __restrict__ bnAb,
    const float* __restrict__ bnAm, const float* __restrict__ bnAv,
    const float* __restrict__ gcnMb,
    const float* __restrict__ bnMg, const float* __restrict__ bnMb,
    const float* __restrict__ bnMm, const float* __restrict__ bnMv,
    const float* __restrict__ mu_, const float* __restrict__ prune_w,
    const float* __restrict__ rewire_w)
{
    __shared__ int sj[MAXDEG + 1];
    __shared__ float se0[MAXDEG + 1], se1[MAXDEG + 1];
    __shared__ int smj[MAXM];
    __shared__ float smc[MAXM];
    __shared__ float rA[256], rB[256];
    int i = blockIdx.x, tid = threadIdx.x;
    int deg = g_adj_cnt[i], tot = deg + 1;
    float ad0 = g_ad[2 * i], ad1 = g_ad[2 * i + 1];
    for (int t = tid; t < tot; t += 256) {
        int j = (t < deg) ? g_adj_idx[i * MAXDEG + t] : i;
        sj[t] = j;
        float e0 = ad0 + g_as[2 * j], e1 = ad1 + g_as[2 * j + 1];
        se0[t] = (e0 > 0.f) ? e0 : 0.2f * e0;
        se1[t] = (e1 > 0.f) ? e1 : 0.2f * e1;
    }
    int mc = g_m_cnt[i];
    for (int t = tid; t < mc; t += 256) {
        int j = g_m_idx[i * MAXM + t];
        smj[t] = j;
        smc[t] = g_m_val[i * MAXM + t] * g_dinvM[j];
    }
    __syncthreads();
    float lm0 = -3.4e38f, lm1 = -3.4e38f;
    for (int t = tid; t < tot; t += 256) { lm0 = fmaxf(lm0, se0[t]); lm1 = fmaxf(lm1, se1[t]); }
    rA[tid] = lm0; rB[tid] = lm1; __syncthreads();
    for (int s = 128; s > 0; s >>= 1) {
        if (tid < s) { rA[tid] = fmaxf(rA[tid], rA[tid + s]); rB[tid] = fmaxf(rB[tid], rB[tid + s]); }
        __syncthreads();
    }
    float M0 = rA[0], M1 = rB[0]; __syncthreads();
    float ls0 = 0.f, ls1 = 0.f;
    for (int t = tid; t < tot; t += 256) {
        float e0 = expf(se0[t] - M0); se0[t] = e0; ls0 += e0;
        float e1 = expf(se1[t] - M1); se1[t] = e1; ls1 += e1;
    }
    rA[tid] = ls0; rB[tid] = ls1; __syncthreads();
    for (int s = 128; s > 0; s >>= 1) {
        if (tid < s) { rA[tid] += rA[tid + s]; rB[tid] += rB[tid + s]; }
        __syncthreads();
    }
    float D0 = rA[0], D1 = rB[0]; __syncthreads();

    int d = tid, head = d >> 7;
    float Dh = head ? D1 : D0;
    const float* se = head ? se1 : se0;
    float accA = 0.f;
    #pragma unroll 4
    for (int k = 0; k < tot; k++) accA += se[k] * g_Wx[(size_t)sj[k] * FH + d];
    float hA = accA / Dh + gat_b[d];
    hA = (hA - bnAm[d]) * bnAg[d] * rsqrtf(bnAv[d] + 1e-5f) + bnAb[d];
    hA = (hA > 0.f) ? hA : expm1f(hA);

    float accM = 0.f;
    #pragma unroll 4
    for (int k = 0; k < mc; k++) accM += smc[k] * g_XWM[(size_t)smj[k] * FH + d];
    float hM = g_dinvM[i] * accM + gcnMb[d];
    hM = (hM - bnMm[d]) * bnMg[d] * rsqrtf(bnMv[d] + 1e-5f) + bnMb[d];
    hM = (hM > 0.f) ? hM : expm1f(hM);

    float mu = mu_[0];
    float sp = (mu > 20.f) ? mu : log1pf(expf(mu));
    float hv = hA + sp * hM;
    g_h[(size_t)i * FH + d] = hv;

    rA[tid] = hv * prune_w[d]; rB[tid] = hv * prune_w[256 + d]; __syncthreads();
    for (int s = 128; s > 0; s >>= 1) {
        if (tid < s) { rA[tid] += rA[tid + s]; rB[tid] += rB[tid + s]; }
        __syncthreads();
    }
    float r0 = rA[0], r1 = rB[0]; __syncthreads();
    rA[tid] = hv * rewire_w[d]; rB[tid] = hv * rewire_w[256 + d]; __syncthreads();
    for (int s = 128; s > 0; s >>= 1) {
        if (tid < s) { rA[tid] += rA[tid + s]; rB[tid] += rB[tid + s]; }
        __syncthreads();
    }
    if (tid == 0) { g_pu[i] = r0; g_pv[i] = r1; g_ru[i] = rA[0]; g_rv[i] = rB[0]; }
}

__global__ void k_cells(const float* __restrict__ coords) {
    int i = blockIdx.x * blockDim.x + threadIdx.x;
    if (i >= NN) return;
    int cx = (int)coords[2 * i], cy = (int)coords[2 * i + 1];
    int p = atomicAdd(&g_cell_cnt[cx * 64 + cy], 1);
    if (p < CELLCAP) g_cell_nodes[(cx * 64 + cy) * CELLCAP + p] = i;
}

__global__ void k_cells_sort() {
    int c = blockIdx.x * blockDim.x + threadIdx.x;
    if (c >= 4096) return;
    int n = min(g_cell_cnt[c], CELLCAP);
    int* a = &g_cell_nodes[c * CELLCAP];
    for (int x = 1; x < n; x++) {
        int v = a[x], y = x - 1;
        while (y >= 0 && a[y] > v) { a[y + 1] = a[y]; y--; }
        a[y + 1] = v;
    }
}

__global__ void k_candidates(const float* __restrict__ coords, const float* __restrict__ A_in,
                             const float* __restrict__ rw, const float* __restrict__ rb_,
                             const float* __restrict__ tau_) {
    int gw = (blockIdx.x * blockDim.x + threadIdx.x) >> 5;
    int lane = threadIdx.x & 31;
    if (gw >= NN) return;
    int i = gw;
    float tau = tau_[0], rw2 = rw[512], rb = rb_[0];
    int cx = (int)coords[2 * i], cy = (int)coords[2 * i + 1];
    const int ox[12] = {-2,-1,-1,-1, 0, 0, 0, 0, 1, 1, 1, 2};
    const int oy[12] = { 0,-1, 0, 1,-2,-1, 1, 2,-1, 0, 1, 0};
    float rui = g_ru[i], rvi = g_rv[i];
    int cnt = 0;
    float m1 = NEGINF, m2 = NEGINF;
    for (int o = 0; o < 12; o++) {
        int nx = cx + ox[o], ny = cy + oy[o];
        if (nx < 0 || nx >= 64 || ny < 0 || ny >= 64) continue;
        int cell = nx * 64 + ny;
        int cc = min(g_cell_cnt[cell], CELLCAP);
        for (int base = 0; base < cc; base += 32) {
            int t = base + lane;
            bool ok = t < cc;
            int j = 0; float z = 0.f;
            if (ok) {
                j = g_cell_nodes[cell * CELLCAP + t];
                ok = A_in[(size_t)i * NN + j] < 1e-6f;
            }
            if (ok) {
                float ruv = (i < j) ? (rui + g_rv[j]) : (g_ru[j] + rvi);
                z = hc_gate(ruv + rw2 * mhat_bs(i, j) + rb, tau);
                if (z > m1) { m2 = m1; m1 = z; } else if (z > m2) { m2 = z; }
            }
            unsigned m = __ballot_sync(~0u, ok);
            int pos = cnt + __popc(m & ((1u << lane) - 1));
            if (ok && pos < MAXC) { g_cand_idx[i * MAXC + pos] = j; g_cand_z[i * MAXC + pos] = z; }
            cnt += __popc(m);
        }
    }
    for (int o = 16; o; o >>= 1) {
        float om1 = __shfl_xor_sync(~0u, m1, o);
        float om2 = __shfl_xor_sync(~0u, m2, o);
        float hi = fmaxf(m1, om1), lo = fminf(m1, om1);
        m2 = fmaxf(lo, fmaxf(m2, om2));
        m1 = hi;
    }
    if (lane == 0) { g_cand_cnt[i] = min(cnt, MAXC); g_thr2[i] = m2; }
}

__global__ void k_refined(const float* __restrict__ prune_w, const float* __restrict__ prune_b,
                          const float* __restrict__ tau_) {
    int gw = (blockIdx.x * blockDim.x + threadIdx.x) >> 5;
    int lane = threadIdx.x & 31;
    if (gw >= NN) return;
    int i = gw;
    float tau = tau_[0], pw2 = prune_w[512], pb = prune_b[0];
    int deg = g_adj_cnt[i];
    float wsum = 0.f;
    for (int t = lane; t < deg; t += 32) {
        int j = g_adj_idx[i * MAXDEG + t];
        float puv = (i < j) ? (g_pu[i] + g_pv[j]) : (g_pu[j] + g_pv[i]);
        float z = hc_gate(puv + pw2 * mhat_bs(i, j) + pb, tau);
        g_ref_idx[i * MAXR + t] = j;
        g_ref_w[i * MAXR + t] = z;
        wsum += z;
    }
    int cnt = deg;
    float thrI = g_thr2[i];
    int cc = g_cand_cnt[i];
    for (int base = 0; base < cc; base += 32) {
        int t = base + lane; bool ok = false; int j = 0; float z = 0.f;
        if (t < cc) {
            j = g_cand_idx[i * MAXC + t]; z = g_cand_z[i * MAXC + t];
            ok = (z >= thrI) || (z >= g_thr2[j]);
        }
        unsigned m = __ballot_sync(0xffffffffu, ok);
        int pos = cnt + __popc(m & ((1u << lane) - 1));
        if (ok) { g_ref_idx[i * MAXR + pos] = j; g_ref_w[i * MAXR + pos] = 0.5f * z; wsum += 0.5f * z; }
        cnt += __popc(m);
    }
    for (int o = 16; o; o >>= 1) wsum += __shfl_down_sync(0xffffffffu, wsum, o);
    if (lane == 0) { g_ref_cnt[i] = cnt; g_dinv_ref[i] = rsqrtf(wsum + 1.f); }
}

__global__ void k_pool(const float* __restrict__ pool_b) {
    __shared__ float red[128];
    int i = blockIdx.x, c = threadIdx.x;
    float di = g_dinv_ref[i];
    int cnt = g_ref_cnt[i];
    float acc = di * g_HW[(size_t)i * CL + c];
    #pragma unroll 4
    for (int t = 0; t < cnt; t++) {
        int j = g_ref_idx[i * MAXR + t];
        acc += g_ref_w[i * MAXR + t] * g_dinv_ref[j] * g_HW[(size_t)j * CL + c];
    }
    float pre = di * acc + pool_b[c];
    red[c] = pre; __syncthreads();
    for (int s = 64; s > 0; s >>= 1) { if (c < s) red[c] = fmaxf(red[c], red[c + s]); __syncthreads(); }
    float mx = red[0]; __syncthreads();
    float e = expf(pre - mx);
    red[c] = e; __syncthreads();
    for (int s = 64; s > 0; s >>= 1) { if (c < s) red[c] += red[c + s]; __syncthreads(); }
    g_S[(size_t)i * CL + c] = e / red[0];
}

__global__ void k_spmmT() {
    int i = blockIdx.x, c = threadIdx.x;
    int cnt = g_ref_cnt[i];
    float acc = 0.f;
    #pragma unroll 4
    for (int t = 0; t < cnt; t++)
        acc += g_ref_w[i * MAXR + t] * g_S[(size_t)g_ref_idx[i * MAXR + t] * CL + c];
    g_T[(size_t)i * CL + c] = acc;
}

__global__ void k_coarse_thr() {
    int gw = (blockIdx.x * blockDim.x + threadIdx.x) >> 5;
    int lane = threadIdx.x & 31;
    if (gw >= 128) return;
    float vv[4];
    #pragma unroll
    for (int s = 0; s < 4; s++) {
        int j = s * 32 + lane;
        vv[s] = (j == gw) ? 0.f : g_Ac[gw * 128 + j];
    }
    float thr = 0.f;
    for (int r = 0; r < 8; r++) {
        float lm = fmaxf(fmaxf(vv[0], vv[1]), fmaxf(vv[2], vv[3]));
        float wm = lm;
        for (int o = 16; o; o >>= 1) wm = fmaxf(wm, __shfl_xor_sync(~0u, wm, o));
        unsigned who = __ballot_sync(~0u, lm == wm);
        if (lane == (__ffs(who) - 1)) {
            #pragma unroll
            for (int s = 0; s < 4; s++) if (vv[s] == wm) { vv[s] = -1e30f; break; }
        }
        thr = wm;
    }
    if (lane == 0) g_cthr[gw] = thr;
}

__global__ void k_coarse_write(float* __restrict__ out) {
    int t = blockIdx.x * blockDim.x + threadIdx.x;
    if (t >= 128 * 128) return;
    int i = t >> 7, j = t & 127;
    if (i == j) { out[t] = 0.f; return; }
    float vij = g_Ac[i * 128 + j];
    float vji = g_Ac[j * 128 + i];
    float a = (vij >= g_cthr[i]) ? vij : 0.f;
    float b = (vji >= g_cthr[j]) ? vji : 0.f;
    out[t] = fmaxf(a, b);
}

// ---------- host ----------
extern "C" void kernel_launch(void* const* d_in, const int* in_sizes, int n_in,
                              void* d_out, int out_size) {
    const float* x       = (const float*)d_in[0];
    const float* A_in    = (const float*)d_in[1];
    const float* A_motif = (const float*)d_in[2];
    const float* coords  = (const float*)d_in[3];
    const float* gat_w   = (const float*)d_in[4];
    const float* gat_as  = (const float*)d_in[5];
    const float* gat_ad  = (const float*)d_in[6];
    const float* gat_b   = (const float*)d_in[7];
    const float* bnAg = (const float*)d_in[8],  *bnAb = (const float*)d_in[9];
    const float* bnAm = (const float*)d_in[10], *bnAv = (const float*)d_in[11];
    const float* gcnMw = (const float*)d_in[12], *gcnMb = (const float*)d_in[13];
    const float* bnMg = (const float*)d_in[14], *bnMb = (const float*)d_in[15];
    const float* bnMm = (const float*)d_in[16], *bnMv = (const float*)d_in[17];
    const float* mu   = (const float*)d_in[18], *tau  = (const float*)d_in[19];
    const float* prune_w = (const float*)d_in[20], *prune_b = (const float*)d_in[21];
    const float* rewire_w = (const float*)d_in[22], *rewire_b = (const float*)d_in[23];
    const float* pool_w = (const float*)d_in[24], *pool_b = (const float*)d_in[25];
    float* out = (float*)d_out;

    float *Wx, *XWM, *h, *HW, *S, *T, *Cpart, *Ac;
    cudaGetSymbolAddress((void**)&Wx, g_Wx);
    cudaGetSymbolAddress((void**)&XWM, g_XWM);
    cudaGetSymbolAddress((void**)&h, g_h);
    cudaGetSymbolAddress((void**)&HW, g_HW);
    cudaGetSymbolAddress((void**)&S, g_S);
    cudaGetSymbolAddress((void**)&T, g_T);
    cudaGetSymbolAddress((void**)&Cpart, g_Cpart);
    cudaGetSymbolAddress((void**)&Ac, g_Ac);

    k_build_adj<<<512, 256>>>(A_in);                                  // 0 (also zeros cells)
    k_build_motif<<<512, 256>>>(A_motif);                             // 1
    k_gemm<<<dim3(FH / 64, NN / 128), 256>>>(x, gat_w, Wx, NN, FH, 128);   // 2
    k_gemm<<<dim3(FH / 64, NN / 128), 256>>>(x, gcnMw, XWM, NN, FH, 128);  // 3 (profiled slot)
    k_mfilter<<<512, 256>>>();                                        // 4
    k_attn_coef<<<1024, 256>>>(gat_as, gat_ad);                       // 5
    k_aggregate<<<NN, 256>>>(gat_b, bnAg, bnAb, bnAm, bnAv, gcnMb,
                             bnMg, bnMb, bnMm, bnMv, mu, prune_w, rewire_w);
    k_cells<<<16, 256>>>(coords);
    k_cells_sort<<<16, 256>>>();
    k_candidates<<<512, 256>>>(coords, A_in, rewire_w, rewire_b, tau);
    k_refined<<<512, 256>>>(prune_w, prune_b, tau);
    k_gemm<<<dim3(CL / 64, NN / 128), 256>>>(h, pool_w, HW, NN, CL, FH);
    k_pool<<<NN, 128>>>(pool_b);
    k_spmmT<<<NN, 128>>>();
    k_gemm_tn<<<dim3(FH / 64, 128 / 64, KS), 256>>>(S, h, Cpart, 128, FH, NN);
    k_reduce_part<<<(128 * FH + 255) / 256, 256>>>(out, 128 * FH);
    k_gemm_tn<<<dim3(CL / 64, 128 / 64, KS), 256>>>(S, T, Cpart, 128, CL, NN);
    k_reduce_part<<<(128 * CL + 255) / 256, 256>>>(Ac, 128 * CL);
    k_coarse_thr<<<16, 256>>>();
    k_coarse_write<<<64, 256>>>(out + 128 * FH);
}

// round 9
// speedup vs baseline: 1.1183x; 1.0671x over previous
#include <cuda_runtime.h>
#include <math.h>

#define NN 4096
#define FH 256
#define CL 128
#define MAXDEG 128
#define MAXM 128
#define MAXC 64
#define MAXR (MAXDEG + MAXC)
#define CELLCAP 32
#define NEGINF (-1e9f)
#define KS 16

// ---------- scratch ----------
__device__ int   g_adj_idx[NN * MAXDEG];
__device__ int   g_adj_cnt[NN];
__device__ int   g_mf_idx[NN * MAXM];
__device__ float g_mf_val[NN * MAXM];
__device__ int   g_mf_cnt[NN];
__device__ float g_m_thr[NN];
__device__ int   g_m_idx[NN * MAXM];
__device__ float g_m_val[NN * MAXM];
__device__ int   g_m_cnt[NN];
__device__ float g_dinvM[NN];
__device__ float g_Wx[NN * FH];
__device__ float g_XWM[NN * FH];
__device__ float g_as[NN * 2];
__device__ float g_ad[NN * 2];
__device__ float g_h[NN * FH];
__device__ float g_pu[NN], g_pv[NN], g_ru[NN], g_rv[NN];
__device__ int   g_cell_cnt[4096];
__device__ int   g_cell_nodes[4096 * CELLCAP];
__device__ int   g_cand_idx[NN * MAXC];
__device__ float g_cand_z[NN * MAXC];
__device__ int   g_cand_cnt[NN];
__device__ float g_thr2[NN];
__device__ int   g_ref_idx[NN * MAXR];
__device__ float g_ref_w[NN * MAXR];
__device__ int   g_ref_cnt[NN];
__device__ float g_dinv_ref[NN];
__device__ float g_HW[NN * CL];
__device__ float g_S[NN * CL];
__device__ float g_T[NN * CL];
__device__ float g_Cpart[KS * 128 * 256];
__device__ float g_Ac[128 * 128];
__device__ float g_cthr[128];

// ---------- helpers ----------
__device__ __forceinline__ float hc_gate(float logit, float tau) {
    float t = fmaxf(tau, 0.1f);
    float s = 1.f / (1.f + expf(-logit / t));
    s = s * 1.2f - 0.1f;
    return fminf(fmaxf(s, 0.f), 1.f);
}
__device__ __forceinline__ float mhat_bs(int i, int j) {
    int c = g_m_cnt[i];
    const int* ip = &g_m_idx[i * MAXM];
    int lo = 0, hi = c;
    while (lo < hi) { int mid = (lo + hi) >> 1; if (ip[mid] < j) lo = mid + 1; else hi = mid; }
    return (lo < c && ip[lo] == j) ? g_m_val[i * MAXM + lo] : 0.f;
}

// ---------- kernels ----------
__global__ void k_build_adj(const float* __restrict__ A) {
    if (blockIdx.x < 16) g_cell_cnt[blockIdx.x * 256 + threadIdx.x] = 0;
    int gw = (blockIdx.x * blockDim.x + threadIdx.x) >> 5;
    int lane = threadIdx.x & 31;
    if (gw >= NN) return;
    const float4* row = (const float4*)(A + (size_t)gw * NN);
    unsigned below = (1u << lane) - 1;
    int c = 0;
    #pragma unroll 4
    for (int b = 0; b < NN / 4; b += 32) {
        float4 v = row[b + lane];
        bool p0 = v.x > 0.f, p1 = v.y > 0.f, p2 = v.z > 0.f, p3 = v.w > 0.f;
        unsigned m0 = __ballot_sync(~0u, p0), m1 = __ballot_sync(~0u, p1);
        unsigned m2 = __ballot_sync(~0u, p2), m3 = __ballot_sync(~0u, p3);
        int base = c + __popc(m0 & below) + __popc(m1 & below) + __popc(m2 & below) + __popc(m3 & below);
        int col = (b + lane) * 4, o = 0;
        if (p0 && base + o < MAXDEG) g_adj_idx[gw * MAXDEG + base + o] = col;
        if (p0) o++;
        if (p1 && base + o < MAXDEG) g_adj_idx[gw * MAXDEG + base + o] = col + 1;
        if (p1) o++;
        if (p2 && base + o < MAXDEG) g_adj_idx[gw * MAXDEG + base + o] = col + 2;
        if (p2) o++;
        if (p3 && base + o < MAXDEG) g_adj_idx[gw * MAXDEG + base + o] = col + 3;
        c += __popc(m0) + __popc(m1) + __popc(m2) + __popc(m3);
    }
    if (lane == 0) g_adj_cnt[gw] = min(c, MAXDEG);
}

__global__ void k_build_motif(const float* __restrict__ A) {
    int gw = (blockIdx.x * blockDim.x + threadIdx.x) >> 5;
    int lane = threadIdx.x & 31;
    if (gw >= NN) return;
    const float4* row = (const float4*)(A + (size_t)gw * NN);
    unsigned below = (1u << lane) - 1;
    int c = 0;
    #pragma unroll 4
    for (int b = 0; b < NN / 4; b += 32) {
        float4 v = row[b + lane];
        bool p0 = v.x > 0.f, p1 = v.y > 0.f, p2 = v.z > 0.f, p3 = v.w > 0.f;
        unsigned m0 = __ballot_sync(~0u, p0), m1 = __ballot_sync(~0u, p1);
        unsigned m2 = __ballot_sync(~0u, p2), m3 = __ballot_sync(~0u, p3);
        int base = c + __popc(m0 & below) + __popc(m1 & below) + __popc(m2 & below) + __popc(m3 & below);
        int col = (b + lane) * 4, o = 0;
        if (p0 && base + o < MAXM) { g_mf_idx[gw * MAXM + base + o] = col;     g_mf_val[gw * MAXM + base + o] = v.x; }
        if (p0) o++;
        if (p1 && base + o < MAXM) { g_mf_idx[gw * MAXM + base + o] = col + 1; g_mf_val[gw * MAXM + base + o] = v.y; }
        if (p1) o++;
        if (p2 && base + o < MAXM) { g_mf_idx[gw * MAXM + base + o] = col + 2; g_mf_val[gw * MAXM + base + o] = v.z; }
        if (p2) o++;
        if (p3 && base + o < MAXM) { g_mf_idx[gw * MAXM + base + o] = col + 3; g_mf_val[gw * MAXM + base + o] = v.w; }
        c += __popc(m0) + __popc(m1) + __popc(m2) + __popc(m3);
    }
    c = min(c, MAXM);
    __syncwarp();
    float vv[4];
    #pragma unroll
    for (int s = 0; s < 4; s++) {
        int t = s * 32 + lane;
        vv[s] = (t < c) ? g_mf_val[gw * MAXM + t] : -2.f;
    }
    float thr = 0.f;
    if (c > 8) {
        for (int r = 0; r < 8; r++) {
            float lm = fmaxf(fmaxf(vv[0], vv[1]), fmaxf(vv[2], vv[3]));
            float wm = lm;
            for (int o = 16; o; o >>= 1) wm = fmaxf(wm, __shfl_xor_sync(~0u, wm, o));
            unsigned who = __ballot_sync(~0u, lm == wm);
            if (lane == (__ffs(who) - 1)) {
                #pragma unroll
                for (int s = 0; s < 4; s++) if (vv[s] == wm) { vv[s] = -2.f; break; }
            }
            thr = wm;
        }
    }
    if (lane == 0) { g_mf_cnt[gw] = c; g_m_thr[gw] = thr; }
}

__global__ void k_mfilter() {
    int gw = (blockIdx.x * blockDim.x + threadIdx.x) >> 5;
    int lane = threadIdx.x & 31;
    if (gw >= NN) return;
    int i = gw, cnt = g_mf_cnt[i], out = 0;
    float thrI = g_m_thr[i], wsum = 0.f;
    for (int base = 0; base < cnt; base += 32) {
        int t = base + lane; bool ok = t < cnt; int j = 0; float v = 0.f;
        if (ok) {
            j = g_mf_idx[i * MAXM + t]; v = g_mf_val[i * MAXM + t];
            ok = (v >= thrI) || (v >= g_m_thr[j]);
        }
        unsigned m = __ballot_sync(0xffffffffu, ok);
        int pos = out + __popc(m & ((1u << lane) - 1));
        if (ok) { g_m_idx[i * MAXM + pos] = j; g_m_val[i * MAXM + pos] = v; wsum += v; }
        out += __popc(m);
    }
    for (int o = 16; o; o >>= 1) wsum += __shfl_down_sync(0xffffffffu, wsum, o);
    if (lane == 0) { g_m_cnt[i] = out; g_dinvM[i] = (wsum > 0.f) ? rsqrtf(wsum) : 0.f; }
}

// C[M,Nc] = A[M,K] @ B[K,Nc]; 64x64 tile, 4x4 micro, DOUBLE-BUFFERED smem.
// K order identical to the original single-buffered kernel -> bit-identical.
__global__ void k_gemm(const float* __restrict__ A, const float* __restrict__ B,
                       float* __restrict__ C, int M, int Nc, int K) {
    __shared__ float As[2][16][65], Bs[2][16][65];
    int bm = blockIdx.y * 64, bn = blockIdx.x * 64;
    int tid = threadIdx.x, tr = tid >> 4, tc = tid & 15;
    int am[4], ak[4], bk[4], bnn[4];
    float ra[4], rb[4];
    #pragma unroll
    for (int l = 0; l < 4; l++) {
        int e = tid + l * 256;
        am[l] = e >> 4; ak[l] = e & 15;
        bk[l] = e >> 6; bnn[l] = e & 63;
    }
    int nP = K / 16;
    #pragma unroll
    for (int l = 0; l < 4; l++) {
        ra[l] = A[(size_t)(bm + am[l]) * K + ak[l]];
        rb[l] = B[(size_t)bk[l] * Nc + bn + bnn[l]];
    }
    #pragma unroll
    for (int l = 0; l < 4; l++) {
        As[0][ak[l]][am[l]] = ra[l];
        Bs[0][bk[l]][bnn[l]] = rb[l];
    }
    __syncthreads();
    float acc[4][4] = {};
    for (int p = 0; p < nP; p++) {
        int cur = p & 1;
        if (p + 1 < nP) {
            int k0 = (p + 1) * 16;
            #pragma unroll
            for (int l = 0; l < 4; l++) {
                ra[l] = A[(size_t)(bm + am[l]) * K + k0 + ak[l]];
                rb[l] = B[(size_t)(k0 + bk[l]) * Nc + bn + bnn[l]];
            }
        }
        #pragma unroll
        for (int kk = 0; kk < 16; kk++) {
            float a[4], b[4];
            #pragma unroll
            for (int r = 0; r < 4; r++) a[r] = As[cur][kk][tr * 4 + r];
            #pragma unroll
            for (int c = 0; c < 4; c++) b[c] = Bs[cur][kk][tc * 4 + c];
            #pragma unroll
            for (int r = 0; r < 4; r++)
                #pragma unroll
                for (int c = 0; c < 4; c++) acc[r][c] += a[r] * b[c];
        }
        if (p + 1 < nP) {
            #pragma unroll
            for (int l = 0; l < 4; l++) {
                As[cur ^ 1][ak[l]][am[l]] = ra[l];
                Bs[cur ^ 1][bk[l]][bnn[l]] = rb[l];
            }
        }
        __syncthreads();
    }
    #pragma unroll
    for (int r = 0; r < 4; r++)
        #pragma unroll
        for (int c = 0; c < 4; c++)
            C[(size_t)(bm + tr * 4 + r) * Nc + bn + tc * 4 + c] = acc[r][c];
}

// Cpart[ks][M,Nc] = A[kslice,M]^T @ B[kslice,Nc]; DOUBLE-BUFFERED.
__global__ void k_gemm_tn(const float* __restrict__ A, const float* __restrict__ B,
                          float* __restrict__ Cpart, int M, int Nc, int K) {
    __shared__ float As[2][16][65], Bs[2][16][65];
    int ks = blockIdx.z, kbeg = ks * (K / KS);
    int nP = (K / KS) / 16;
    int bm = blockIdx.y * 64, bn = blockIdx.x * 64;
    int tid = threadIdx.x, tr = tid >> 4, tc = tid & 15;
    int lk[4], ln[4];
    float ra[4], rb[4];
    #pragma unroll
    for (int l = 0; l < 4; l++) {
        int e = tid + l * 256;
        lk[l] = e >> 6; ln[l] = e & 63;
    }
    #pragma unroll
    for (int l = 0; l < 4; l++) {
        ra[l] = A[(size_t)(kbeg + lk[l]) * M + bm + ln[l]];
        rb[l] = B[(size_t)(kbeg + lk[l]) * Nc + bn + ln[l]];
    }
    #pragma unroll
    for (int l = 0; l < 4; l++) {
        As[0][lk[l]][ln[l]] = ra[l];
        Bs[0][lk[l]][ln[l]] = rb[l];
    }
    __syncthreads();
    float acc[4][4] = {};
    for (int p = 0; p < nP; p++) {
        int cur = p & 1;
        if (p + 1 < nP) {
            int k0 = kbeg + (p + 1) * 16;
            #pragma unroll
            for (int l = 0; l < 4; l++) {
                ra[l] = A[(size_t)(k0 + lk[l]) * M + bm + ln[l]];
                rb[l] = B[(size_t)(k0 + lk[l]) * Nc + bn + ln[l]];
            }
        }
        #pragma unroll
        for (int kk = 0; kk < 16; kk++) {
            float a[4], b[4];
            #pragma unroll
            for (int r = 0; r < 4; r++) a[r] = As[cur][kk][tr * 4 + r];
            #pragma unroll
            for (int c = 0; c < 4; c++) b[c] = Bs[cur][kk][tc * 4 + c];
            #pragma unroll
            for (int r = 0; r < 4; r++)
                #pragma unroll
                for (int c = 0; c < 4; c++) acc[r][c] += a[r] * b[c];
        }
        if (p + 1 < nP) {
            #pragma unroll
            for (int l = 0; l < 4; l++) {
                As[cur ^ 1][lk[l]][ln[l]] = ra[l];
                Bs[cur ^ 1][lk[l]][ln[l]] = rb[l];
            }
        }
        __syncthreads();
    }
    float* Cp = Cpart + (size_t)ks * M * Nc;
    #pragma unroll
    for (int r = 0; r < 4; r++)
        #pragma unroll
        for (int c = 0; c < 4; c++)
            Cp[(size_t)(bm + tr * 4 + r) * Nc + bn + tc * 4 + c] = acc[r][c];
}

__global__ void k_reduce_part(float* __restrict__ dst, int MN) {
    int t = blockIdx.x * blockDim.x + threadIdx.x;
    if (t >= MN) return;
    float s = 0.f;
    for (int z = 0; z < KS; z++) s += g_Cpart[(size_t)z * MN + t];
    dst[t] = s;
}

__global__ void k_attn_coef(const float* __restrict__ asw, const float* __restrict__ adw) {
    int gw = (blockIdx.x * blockDim.x + threadIdx.x) >> 5;
    int lane = threadIdx.x & 31;
    if (gw >= NN * 2) return;
    int node = gw >> 1, hh = gw & 1;
    const float* row = g_Wx + (size_t)node * FH + hh * 128;
    float s = 0.f, d = 0.f;
    for (int k = lane; k < 128; k += 32) {
        float w = row[k];
        s += w * asw[hh * 128 + k];
        d += w * adw[hh * 128 + k];
    }
    for (int o = 16; o; o >>= 1) {
        s += __shfl_down_sync(0xffffffffu, s, o);
        d += __shfl_down_sync(0xffffffffu, d, o);
    }
    if (lane == 0) { g_as[node * 2 + hh] = s; g_ad[node * 2 + hh] = d; }
}

__global__ void k_aggregate(
    const float* __restrict__ gat_b,
    const float* __restrict__ bnAg, const float* __restrict__ bnAb,
    const float* __restrict__ bnAm, const float* __restrict__ bnAv,
    const float* __restrict__ gcnMb,
    const float* __restrict__ bnMg, const float* __restrict__ bnMb,
    const float* __restrict__ bnMm, const float* __restrict__ bnMv,
    const float* __restrict__ mu_, const float* __restrict__ prune_w,
    const float* __restrict__ rewire_w)
{
    __shared__ int sj[MAXDEG + 1];
    __shared__ float se0[MAXDEG + 1], se1[MAXDEG + 1];
    __shared__ int smj[MAXM];
    __shared__ float smc[MAXM];
    __shared__ float rA[256], rB[256];
    int i = blockIdx.x, tid = threadIdx.x;
    int deg = g_adj_cnt[i], tot = deg + 1;
    float ad0 = g_ad[2 * i], ad1 = g_ad[2 * i + 1];
    for (int t = tid; t < tot; t += 256) {
        int j = (t < deg) ? g_adj_idx[i * MAXDEG + t] : i;
        sj[t] = j;
        float e0 = ad0 + g_as[2 * j], e1 = ad1 + g_as[2 * j + 1];
        se0[t] = (e0 > 0.f) ? e0 : 0.2f * e0;
        se1[t] = (e1 > 0.f) ? e1 : 0.2f * e1;
    }
    int mc = g_m_cnt[i];
    for (int t = tid; t < mc; t += 256) {
        int j = g_m_idx[i * MAXM + t];
        smj[t] = j;
        smc[t] = g_m_val[i * MAXM + t] * g_dinvM[j];
    }
    __syncthreads();
    float lm0 = -3.4e38f, lm1 = -3.4e38f;
    for (int t = tid; t < tot; t += 256) { lm0 = fmaxf(lm0, se0[t]); lm1 = fmaxf(lm1, se1[t]); }
    rA[tid] = lm0; rB[tid] = lm1; __syncthreads();
    for (int s = 128; s > 0; s >>= 1) {
        if (tid < s) { rA[tid] = fmaxf(rA[tid], rA[tid + s]); rB[tid] = fmaxf(rB[tid], rB[tid + s]); }
        __syncthreads();
    }
    float M0 = rA[0], M1 = rB[0]; __syncthreads();
    float ls0 = 0.f, ls1 = 0.f;
    for (int t = tid; t < tot; t += 256) {
        float e0 = expf(se0[t] - M0); se0[t] = e0; ls0 += e0;
        float e1 = expf(se1[t] - M1); se1[t] = e1; ls1 += e1;
    }
    rA[tid] = ls0; rB[tid] = ls1; __syncthreads();
    for (int s = 128; s > 0; s >>= 1) {
        if (tid < s) { rA[tid] += rA[tid + s]; rB[tid] += rB[tid + s]; }
        __syncthreads();
    }
    float D0 = rA[0], D1 = rB[0]; __syncthreads();

    int d = tid, head = d >> 7;
    float Dh = head ? D1 : D0;
    const float* se = head ? se1 : se0;
    float accA = 0.f;
    #pragma unroll 4
    for (int k = 0; k < tot; k++) accA += se[k] * g_Wx[(size_t)sj[k] * FH + d];
    float hA = accA / Dh + gat_b[d];
    hA = (hA - bnAm[d]) * bnAg[d] * rsqrtf(bnAv[d] + 1e-5f) + bnAb[d];
    hA = (hA > 0.f) ? hA : expm1f(hA);

    float accM = 0.f;
    #pragma unroll 4
    for (int k = 0; k < mc; k++) accM += smc[k] * g_XWM[(size_t)smj[k] * FH + d];
    float hM = g_dinvM[i] * accM + gcnMb[d];
    hM = (hM - bnMm[d]) * bnMg[d] * rsqrtf(bnMv[d] + 1e-5f) + bnMb[d];
    hM = (hM > 0.f) ? hM : expm1f(hM);

    float mu = mu_[0];
    float sp = (mu > 20.f) ? mu : log1pf(expf(mu));
    float hv = hA + sp * hM;
    g_h[(size_t)i * FH + d] = hv;

    rA[tid] = hv * prune_w[d]; rB[tid] = hv * prune_w[256 + d]; __syncthreads();
    for (int s = 128; s > 0; s >>= 1) {
        if (tid < s) { rA[tid] += rA[tid + s]; rB[tid] += rB[tid + s]; }
        __syncthreads();
    }
    float r0 = rA[0], r1 = rB[0]; __syncthreads();
    rA[tid] = hv * rewire_w[d]; rB[tid] = hv * rewire_w[256 + d]; __syncthreads();
    for (int s = 128; s > 0; s >>= 1) {
        if (tid < s) { rA[tid] += rA[tid + s]; rB[tid] += rB[tid + s]; }
        __syncthreads();
    }
    if (tid == 0) { g_pu[i] = r0; g_pv[i] = r1; g_ru[i] = rA[0]; g_rv[i] = rB[0]; }
}

__global__ void k_cells(const float* __restrict__ coords) {
    int i = blockIdx.x * blockDim.x + threadIdx.x;
    if (i >= NN) return;
    int cx = (int)coords[2 * i], cy = (int)coords[2 * i + 1];
    int p = atomicAdd(&g_cell_cnt[cx * 64 + cy], 1);
    if (p < CELLCAP) g_cell_nodes[(cx * 64 + cy) * CELLCAP + p] = i;
}

__global__ void k_cells_sort() {
    int c = blockIdx.x * blockDim.x + threadIdx.x;
    if (c >= 4096) return;
    int n = min(g_cell_cnt[c], CELLCAP);
    int* a = &g_cell_nodes[c * CELLCAP];
    for (int x = 1; x < n; x++) {
        int v = a[x], y = x - 1;
        while (y >= 0 && a[y] > v) { a[y + 1] = a[y]; y--; }
        a[y + 1] = v;
    }
}

__global__ void k_candidates(const float* __restrict__ coords, const float* __restrict__ A_in,
                             const float* __restrict__ rw, const float* __restrict__ rb_,
                             const float* __restrict__ tau_) {
    int gw = (blockIdx.x * blockDim.x + threadIdx.x) >> 5;
    int lane = threadIdx.x & 31;
    if (gw >= NN) return;
    int i = gw;
    float tau = tau_[0], rw2 = rw[512], rb = rb_[0];
    int cx = (int)coords[2 * i], cy = (int)coords[2 * i + 1];
    const int ox[12] = {-2,-1,-1,-1, 0, 0, 0, 0, 1, 1, 1, 2};
    const int oy[12] = { 0,-1, 0, 1,-2,-1, 1, 2,-1, 0, 1, 0};
    float rui = g_ru[i], rvi = g_rv[i];
    int cnt = 0;
    float m1 = NEGINF, m2 = NEGINF;
    for (int o = 0; o < 12; o++) {
        int nx = cx + ox[o], ny = cy + oy[o];
        if (nx < 0 || nx >= 64 || ny < 0 || ny >= 64) continue;
        int cell = nx * 64 + ny;
        int cc = min(g_cell_cnt[cell], CELLCAP);
        for (int base = 0; base < cc; base += 32) {
            int t = base + lane;
            bool ok = t < cc;
            int j = 0; float z = 0.f;
            if (ok) {
                j = g_cell_nodes[cell * CELLCAP + t];
                ok = A_in[(size_t)i * NN + j] < 1e-6f;
            }
            if (ok) {
                float ruv = (i < j) ? (rui + g_rv[j]) : (g_ru[j] + rvi);
                z = hc_gate(ruv + rw2 * mhat_bs(i, j) + rb, tau);
                if (z > m1) { m2 = m1; m1 = z; } else if (z > m2) { m2 = z; }
            }
            unsigned m = __ballot_sync(~0u, ok);
            int pos = cnt + __popc(m & ((1u << lane) - 1));
            if (ok && pos < MAXC) { g_cand_idx[i * MAXC + pos] = j; g_cand_z[i * MAXC + pos] = z; }
            cnt += __popc(m);
        }
    }
    for (int o = 16; o; o >>= 1) {
        float om1 = __shfl_xor_sync(~0u, m1, o);
        float om2 = __shfl_xor_sync(~0u, m2, o);
        float hi = fmaxf(m1, om1), lo = fminf(m1, om1);
        m2 = fmaxf(lo, fmaxf(m2, om2));
        m1 = hi;
    }
    if (lane == 0) { g_cand_cnt[i] = min(cnt, MAXC); g_thr2[i] = m2; }
}

__global__ void k_refined(const float* __restrict__ prune_w, const float* __restrict__ prune_b,
                          const float* __restrict__ tau_) {
    int gw = (blockIdx.x * blockDim.x + threadIdx.x) >> 5;
    int lane = threadIdx.x & 31;
    if (gw >= NN) return;
    int i = gw;
    float tau = tau_[0], pw2 = prune_w[512], pb = prune_b[0];
    int deg = g_adj_cnt[i];
    float wsum = 0.f;
    for (int t = lane; t < deg; t += 32) {
        int j = g_adj_idx[i * MAXDEG + t];
        float puv = (i < j) ? (g_pu[i] + g_pv[j]) : (g_pu[j] + g_pv[i]);
        float z = hc_gate(puv + pw2 * mhat_bs(i, j) + pb, tau);
        g_ref_idx[i * MAXR + t] = j;
        g_ref_w[i * MAXR + t] = z;
        wsum += z;
    }
    int cnt = deg;
    float thrI = g_thr2[i];
    int cc = g_cand_cnt[i];
    for (int base = 0; base < cc; base += 32) {
        int t = base + lane; bool ok = false; int j = 0; float z = 0.f;
        if (t < cc) {
            j = g_cand_idx[i * MAXC + t]; z = g_cand_z[i * MAXC + t];
            ok = (z >= thrI) || (z >= g_thr2[j]);
        }
        unsigned m = __ballot_sync(0xffffffffu, ok);
        int pos = cnt + __popc(m & ((1u << lane) - 1));
        if (ok) { g_ref_idx[i * MAXR + pos] = j; g_ref_w[i * MAXR + pos] = 0.5f * z; wsum += 0.5f * z; }
        cnt += __popc(m);
    }
    for (int o = 16; o; o >>= 1) wsum += __shfl_down_sync(0xffffffffu, wsum, o);
    if (lane == 0) { g_ref_cnt[i] = cnt; g_dinv_ref[i] = rsqrtf(wsum + 1.f); }
}

__global__ void k_pool(const float* __restrict__ pool_b) {
    __shared__ float red[128];
    int i = blockIdx.x, c = threadIdx.x;
    float di = g_dinv_ref[i];
    int cnt = g_ref_cnt[i];
    float acc = di * g_HW[(size_t)i * CL + c];
    #pragma unroll 4
    for (int t = 0; t < cnt; t++) {
        int j = g_ref_idx[i * MAXR + t];
        acc += g_ref_w[i * MAXR + t] * g_dinv_ref[j] * g_HW[(size_t)j * CL + c];
    }
    float pre = di * acc + pool_b[c];
    red[c] = pre; __syncthreads();
    for (int s = 64; s > 0; s >>= 1) { if (c < s) red[c] = fmaxf(red[c], red[c + s]); __syncthreads(); }
    float mx = red[0]; __syncthreads();
    float e = expf(pre - mx);
    red[c] = e; __syncthreads();
    for (int s = 64; s > 0; s >>= 1) { if (c < s) red[c] += red[c + s]; __syncthreads(); }
    g_S[(size_t)i * CL + c] = e / red[0];
}

__global__ void k_spmmT() {
    int i = blockIdx.x, c = threadIdx.x;
    int cnt = g_ref_cnt[i];
    float acc = 0.f;
    #pragma unroll 4
    for (int t = 0; t < cnt; t++)
        acc += g_ref_w[i * MAXR + t] * g_S[(size_t)g_ref_idx[i * MAXR + t] * CL + c];
    g_T[(size_t)i * CL + c] = acc;
}

__global__ void k_coarse_thr() {
    int gw = (blockIdx.x * blockDim.x + threadIdx.x) >> 5;
    int lane = threadIdx.x & 31;
    if (gw >= 128) return;
    float vv[4];
    #pragma unroll
    for (int s = 0; s < 4; s++) {
        int j = s * 32 + lane;
        vv[s] = (j == gw) ? 0.f : g_Ac[gw * 128 + j];
    }
    float thr = 0.f;
    for (int r = 0; r < 8; r++) {
        float lm = fmaxf(fmaxf(vv[0], vv[1]), fmaxf(vv[2], vv[3]));
        float wm = lm;
        for (int o = 16; o; o >>= 1) wm = fmaxf(wm, __shfl_xor_sync(~0u, wm, o));
        unsigned who = __ballot_sync(~0u, lm == wm);
        if (lane == (__ffs(who) - 1)) {
            #pragma unroll
            for (int s = 0; s < 4; s++) if (vv[s] == wm) { vv[s] = -1e30f; break; }
        }
        thr = wm;
    }
    if (lane == 0) g_cthr[gw] = thr;
}

__global__ void k_coarse_write(float* __restrict__ out) {
    int t = blockIdx.x * blockDim.x + threadIdx.x;
    if (t >= 128 * 128) return;
    int i = t >> 7, j = t & 127;
    if (i == j) { out[t] = 0.f; return; }
    float vij = g_Ac[i * 128 + j];
    float vji = g_Ac[j * 128 + i];
    float a = (vij >= g_cthr[i]) ? vij : 0.f;
    float b = (vji >= g_cthr[j]) ? vji : 0.f;
    out[t] = fmaxf(a, b);
}

// ---------- host ----------
extern "C" void kernel_launch(void* const* d_in, const int* in_sizes, int n_in,
                              void* d_out, int out_size) {
    const float* x       = (const float*)d_in[0];
    const float* A_in    = (const float*)d_in[1];
    const float* A_motif = (const float*)d_in[2];
    const float* coords  = (const float*)d_in[3];
    const float* gat_w   = (const float*)d_in[4];
    const float* gat_as  = (const float*)d_in[5];
    const float* gat_ad  = (const float*)d_in[6];
    const float* gat_b   = (const float*)d_in[7];
    const float* bnAg = (const float*)d_in[8],  *bnAb = (const float*)d_in[9];
    const float* bnAm = (const float*)d_in[10], *bnAv = (const float*)d_in[11];
    const float* gcnMw = (const float*)d_in[12], *gcnMb = (const float*)d_in[13];
    const float* bnMg = (const float*)d_in[14], *bnMb = (const float*)d_in[15];
    const float* bnMm = (const float*)d_in[16], *bnMv = (const float*)d_in[17];
    const float* mu   = (const float*)d_in[18], *tau  = (const float*)d_in[19];
    const float* prune_w = (const float*)d_in[20], *prune_b = (const float*)d_in[21];
    const float* rewire_w = (const float*)d_in[22], *rewire_b = (const float*)d_in[23];
    const float* pool_w = (const float*)d_in[24], *pool_b = (const float*)d_in[25];
    float* out = (float*)d_out;

    float *Wx, *XWM, *h, *HW, *S, *T, *Cpart, *Ac;
    cudaGetSymbolAddress((void**)&Wx, g_Wx);
    cudaGetSymbolAddress((void**)&XWM, g_XWM);
    cudaGetSymbolAddress((void**)&h, g_h);
    cudaGetSymbolAddress((void**)&HW, g_HW);
    cudaGetSymbolAddress((void**)&S, g_S);
    cudaGetSymbolAddress((void**)&T, g_T);
    cudaGetSymbolAddress((void**)&Cpart, g_Cpart);
    cudaGetSymbolAddress((void**)&Ac, g_Ac);

    k_build_adj<<<512, 256>>>(A_in);
    k_build_motif<<<512, 256>>>(A_motif);
    k_gemm<<<dim3(FH / 64, NN / 64), 256>>>(x, gat_w, Wx, NN, FH, 128);
    k_gemm<<<dim3(FH / 64, NN / 64), 256>>>(x, gcnMw, XWM, NN, FH, 128);  // profiled slot
    k_mfilter<<<512, 256>>>();
    k_attn_coef<<<1024, 256>>>(gat_as, gat_ad);
    k_aggregate<<<NN, 256>>>(gat_b, bnAg, bnAb, bnAm, bnAv, gcnMb,
                             bnMg, bnMb, bnMm, bnMv, mu, prune_w, rewire_w);
    k_cells<<<16, 256>>>(coords);
    k_cells_sort<<<16, 256>>>();
    k_candidates<<<512, 256>>>(coords, A_in, rewire_w, rewire_b, tau);
    k_refined<<<512, 256>>>(prune_w, prune_b, tau);
    k_gemm<<<dim3(CL / 64, NN / 64), 256>>>(h, pool_w, HW, NN, CL, FH);
    k_pool<<<NN, 128>>>(pool_b);
    k_spmmT<<<NN, 128>>>();
    k_gemm_tn<<<dim3(FH / 64, 128 / 64, KS), 256>>>(S, h, Cpart, 128, FH, NN);
    k_reduce_part<<<(128 * FH + 255) / 256, 256>>>(out, 128 * FH);
    k_gemm_tn<<<dim3(CL / 64, 128 / 64, KS), 256>>>(S, T, Cpart, 128, CL, NN);
    k_reduce_part<<<(128 * CL + 255) / 256, 256>>>(Ac, 128 * CL);
    k_coarse_thr<<<16, 256>>>();
    k_coarse_write<<<64, 256>>>(out + 128 * FH);
}